// round 3
// baseline (speedup 1.0000x reference)
#include <cuda_runtime.h>

// x (16, 4096, 1024) fp32  ->  out[b][d] = sum_t x[b][t][d]   (16, 1024) fp32
// Single fused HBM-streaming kernel. Per-batch last-block election does the
// cross-slice reduction (order-fixed -> deterministic). No second launch.

#define BATCH   16
#define T_DIM   4096
#define D_DIM   1024
#define T_SPLIT 64                       // blocks along T per batch -> 1024 CTAs total
#define T_PER   (T_DIM / T_SPLIT)        // 64 rows per block
#define D_VEC   (D_DIM / 4)              // 256 float4 per row -> 256 threads/block

// Partial sums: [BATCH][T_SPLIT][D_DIM] = 16*64*1024 floats = 4 MiB
__device__ float    g_partial[BATCH * T_SPLIT * D_DIM];
__device__ unsigned g_count[BATCH];      // zero-initialized; reset after each use

__device__ __forceinline__ float4 ldcs4(const float4* p) {
    float4 v;
    asm volatile("ld.global.cs.v4.f32 {%0,%1,%2,%3}, [%4];"
                 : "=f"(v.x), "=f"(v.y), "=f"(v.z), "=f"(v.w) : "l"(p));
    return v;
}

__global__ void __launch_bounds__(D_VEC) sum_fused(const float* __restrict__ x,
                                                   float* __restrict__ out) {
    const int s  = blockIdx.x;       // T-slice
    const int b  = blockIdx.y;       // batch
    const int dv = threadIdx.x;      // float4 index within D

    // ---- phase 1: stream this block's contiguous 256 KiB chunk ----
    const float4* base = reinterpret_cast<const float4*>(
        x + ((size_t)b * T_DIM + (size_t)s * T_PER) * D_DIM) + dv;
    const int rowStride = D_DIM / 4;   // 256 float4 between consecutive t rows

    float4 a0 = make_float4(0.f, 0.f, 0.f, 0.f);
    float4 a1 = a0, a2 = a0, a3 = a0;

    #pragma unroll 4
    for (int t = 0; t < T_PER; t += 4) {
        float4 v0 = ldcs4(base + (size_t)(t + 0) * rowStride);
        float4 v1 = ldcs4(base + (size_t)(t + 1) * rowStride);
        float4 v2 = ldcs4(base + (size_t)(t + 2) * rowStride);
        float4 v3 = ldcs4(base + (size_t)(t + 3) * rowStride);
        a0.x += v0.x; a0.y += v0.y; a0.z += v0.z; a0.w += v0.w;
        a1.x += v1.x; a1.y += v1.y; a1.z += v1.z; a1.w += v1.w;
        a2.x += v2.x; a2.y += v2.y; a2.z += v2.z; a2.w += v2.w;
        a3.x += v3.x; a3.y += v3.y; a3.z += v3.z; a3.w += v3.w;
    }

    float4 r;
    r.x = (a0.x + a1.x) + (a2.x + a3.x);
    r.y = (a0.y + a1.y) + (a2.y + a3.y);
    r.z = (a0.z + a1.z) + (a2.z + a3.z);
    r.w = (a0.w + a1.w) + (a2.w + a3.w);

    float* pbase = g_partial + ((size_t)b * T_SPLIT + s) * D_DIM;
    reinterpret_cast<float4*>(pbase)[dv] = r;

    // ---- election: last block of this batch reduces across slices ----
    __threadfence();
    __shared__ int sh_last;
    if (threadIdx.x == 0)
        sh_last = (atomicAdd(&g_count[b], 1u) == T_SPLIT - 1);
    __syncthreads();

    if (sh_last) {
        __threadfence();   // acquire: make all slices' partials visible
        const float4* pb = reinterpret_cast<const float4*>(
            g_partial + (size_t)b * T_SPLIT * D_DIM) + dv;
        float4 acc = make_float4(0.f, 0.f, 0.f, 0.f);
        #pragma unroll 8
        for (int s2 = 0; s2 < T_SPLIT; ++s2) {   // fixed order -> deterministic
            float4 v = pb[(size_t)s2 * rowStride];
            acc.x += v.x; acc.y += v.y; acc.z += v.z; acc.w += v.w;
        }
        reinterpret_cast<float4*>(out + (size_t)b * D_DIM)[dv] = acc;

        __syncthreads();                 // all reads of g_count's epoch done
        if (threadIdx.x == 0) g_count[b] = 0;   // reset for next graph replay
    }
}

extern "C" void kernel_launch(void* const* d_in, const int* in_sizes, int n_in,
                              void* d_out, int out_size) {
    const float* x = (const float*)d_in[0];
    float* out = (float*)d_out;

    dim3 grid(T_SPLIT, BATCH);          // 64 x 16 = 1024 CTAs, one full wave
    sum_fused<<<grid, D_VEC>>>(x, out);
    (void)in_sizes; (void)n_in; (void)out_size;
}